// round 17
// baseline (speedup 1.0000x reference)
#include <cuda_runtime.h>
#include <math_constants.h>

#define NORB   1024
#define NTIMES 1024
#define NFZ    24
#define NKEZ   6
#define NTINT  64
#define NALPHA 512

#define HTINT  16                       // tints per CTA (quarter of 64)
#define RS     20                       // slab row stride in floats (80B = 5x16B, quad-aligned)

#define NTHREADS 512
#define NWARPS   16
#define ORB_PER_WARP (NORB / NWARPS)    // 64

#define SLAB_FLOATS  (NALPHA * RS)      // 10240
#define SMEM_BYTES   (SLAB_FLOATS * 4)  // 40960 B -> 4 CTAs/SM (163840 B)

// device scratch: per (epoch, orbit): {dMag_masked, (dal_23<<9)|s}
__device__ float2 g_pk[NTIMES * NORB];

// ---------------- pre-kernel: packed stage, transposed ----------------------
__global__ __launch_bounds__(1024)
void stage_kernel(const float* __restrict__ alpha,
                  const float* __restrict__ dMag,
                  const float* __restrict__ alphas)
{
    __shared__ float2 tile[32][33];
    const int tx = threadIdx.x, ty = threadIdx.y;
    const int t = blockIdx.x * 32 + tx;            // epoch (coalesced read dim)
    const int o = blockIdx.y * 32 + ty;            // orbit

    const float a_lo   = alphas[0];
    const float a_hi   = alphas[NALPHA - 1];
    // alpha index path is CONTINUOUS in aind -> fast log safe (fZ bin is not).
    const float L10    = 0.434294481903251827651f; // 1/ln(10)
    const float la0    = log10f(a_lo);
    const float inv_la = 1.0f / (log10f(alphas[1]) - la0);

    float av = alpha[(size_t)o * NTIMES + t];
    float dm = dMag [(size_t)o * NTIMES + t];
    bool  m  = (av >= a_lo) && (av <= a_hi);
    float aind = (__logf(av) * L10 - la0) * inv_la;
    int a0 = (int)aind;                            // trunc toward zero == astype(int32)
    a0 = max(0, min(a0, NALPHA - 1));
    float dal = aind - (float)a0;                  // dalpha vs clipped a0 (reference quirk)
    int s = min(a0, NALPHA - 2);                   // dynamic_slice clamp
    if (!m) dm = CUDART_INF_F;                     // geom_mask folded

    float dc = fminf(fmaxf(dal, 0.0f), 0.99999988f);
    unsigned dal_m = (unsigned)(dc * 8388608.0f);  // 23-bit fixed point
    unsigned pk = (dal_m << 9) | (unsigned)s;

    tile[ty][tx] = make_float2(dm, __uint_as_float(pk));
    __syncthreads();

    const int tw = blockIdx.x * 32 + ty;
    const int ow = blockIdx.y * 32 + tx;
    g_pk[(size_t)tw * NORB + ow] = tile[tx][ty];
}

// ---------------- main kernel: one CTA = (epoch, tint-quarter) --------------
__global__ __launch_bounds__(NTHREADS, 4)
void pdet_kernel(const float* __restrict__ fZ_vals,
                 const float* __restrict__ kEZ_val,
                 const float* __restrict__ grid,
                 const float* __restrict__ fZs,
                 const float* __restrict__ kEZs,
                 float* __restrict__ out)
{
    extern __shared__ float sm[];
    float* slab = sm;                              // [NALPHA][RS] alpha-major

    const int t   = blockIdx.x;
    const int h   = blockIdx.y;                    // tint quarter (0..3)
    const int tid = threadIdx.x;
    const int w    = tid >> 5;
    const int lane = tid & 31;
    const int k4   = lane & 3;                     // tint quad (0..3) -> tints 4*k4..4*k4+3
    const int slot = lane >> 2;                    // orbit slot within group (0..7)

    // ---- fZ bin (accurate log10f: discontinuous) + kEZ index ----
    const float lf0    = log10f(fZs[0]);
    const float inv_lf = 1.0f / (log10f(fZs[1]) - lf0);
    const float kv = kEZ_val[0];
    int kez = -1;
    #pragma unroll
    for (int i = 0; i < NKEZ; ++i) kez += (kEZs[i] <= kv) ? 1 : 0;
    kez = max(0, min(kez, NKEZ - 1));

    float find = (log10f(fZ_vals[t]) - lf0) * inv_lf;
    int f0 = (int)floorf(find) + 1;
    f0 = max(0, min(f0, NFZ - 2));

    // ---- fill slab transposed: slab[a*RS + j] = grid[f0, kez, h*16+j, a] ----
    // a = tid: coalesced LDGs; STS.128 quad-banks (5*tid)%8 distinct -> cf.
    const float* src = grid
        + ((size_t)(f0 * NKEZ + kez) * NTINT + h * HTINT) * NALPHA;
    #pragma unroll
    for (int jq = 0; jq < HTINT / 4; ++jq) {
        float e0 = src[(4 * jq + 0) * NALPHA + tid];
        float e1 = src[(4 * jq + 1) * NALPHA + tid];
        float e2 = src[(4 * jq + 2) * NALPHA + tid];
        float e3 = src[(4 * jq + 3) * NALPHA + tid];
        *(float4*)(slab + tid * RS + 4 * jq) = make_float4(e0, e1, e2, e3);
    }
    __syncthreads();

    // ---- main loop: warp w -> 64 orbits; 8 orbits/group x 4 lanes x 4 tints
    const float* base = slab + 4 * k4;             // this lane's tint quad
    const float2* gq = g_pk + (size_t)t * NORB + (size_t)(w * ORB_PER_WARP);
    int c0 = 0, c1 = 0, c2 = 0, c3 = 0;

    float2 q = __ldg(gq + slot);                   // group 0: this slot's orbit
    #pragma unroll 2
    for (int b = 0; b < ORB_PER_WARP / 8; ++b) {
        int nb = (b < ORB_PER_WARP / 8 - 1) ? (b + 1) : b;
        float2 qn = __ldg(gq + nb * 8 + slot);     // prefetch next group (64B coalesced)

        unsigned u = __float_as_uint(q.y);
        const float4* p = (const float4*)(base + (u & 511u) * RS);

        float4 g0 = p[0];                          // 4 tints at alpha s
        float4 g1 = p[RS / 4];                     // alpha s+1 (+80B immediate)

        float dal = __uint_as_float((u >> 9) | 0x3F800000u) - 1.0f;
        float dmv = q.x;

        float d;
        d = fmaf(dal, g1.x - g0.x, g0.x); c0 += (dmv < d);
        d = fmaf(dal, g1.y - g0.y, g0.y); c1 += (dmv < d);
        d = fmaf(dal, g1.z - g0.z, g0.z); c2 += (dmv < d);
        d = fmaf(dal, g1.w - g0.w, g0.w); c3 += (dmv < d);

        q = qn;
    }
    // fold the 8 orbit slots (lane bits 2,3,4)
    #pragma unroll
    for (int sh = 4; sh <= 16; sh <<= 1) {
        c0 += __shfl_xor_sync(0xFFFFFFFFu, c0, sh);
        c1 += __shfl_xor_sync(0xFFFFFFFFu, c1, sh);
        c2 += __shfl_xor_sync(0xFFFFFFFFu, c2, sh);
        c3 += __shfl_xor_sync(0xFFFFFFFFu, c3, sh);
    }

    // ---- reduce: red aliases slab after all reads complete ----
    __syncthreads();
    int4* red4 = (int4*)slab;                      // [NWARPS][4] int4 = [NWARPS][16] int
    if (lane < 4)
        red4[w * 4 + k4] = make_int4(c0, c1, c2, c3);
    __syncthreads();

    if (tid < HTINT) {
        const int* red = (const int*)slab;
        int csum = 0;
        #pragma unroll
        for (int ww = 0; ww < NWARPS; ++ww) csum += red[ww * HTINT + tid];
        out[t * NTINT + h * HTINT + tid] = (float)csum * (1.0f / NORB);
    }
}

extern "C" void kernel_launch(void* const* d_in, const int* in_sizes, int n_in,
                              void* d_out, int out_size)
{
    (void)in_sizes; (void)n_in; (void)out_size;
    const float* alpha   = (const float*)d_in[0];
    const float* dMag    = (const float*)d_in[1];
    const float* fZ_vals = (const float*)d_in[2];
    const float* kEZ_val = (const float*)d_in[3];
    const float* grid    = (const float*)d_in[4];
    const float* fZs     = (const float*)d_in[5];
    const float* kEZs    = (const float*)d_in[6];
    const float* alphas  = (const float*)d_in[7];
    float* out = (float*)d_out;

    dim3 sgrid(NTIMES / 32, NORB / 32);
    stage_kernel<<<sgrid, dim3(32, 32)>>>(alpha, dMag, alphas);

    cudaFuncSetAttribute(pdet_kernel,
                         cudaFuncAttributeMaxDynamicSharedMemorySize, SMEM_BYTES);
    dim3 mgrid(NTIMES, NTINT / HTINT);
    pdet_kernel<<<mgrid, NTHREADS, SMEM_BYTES>>>(fZ_vals, kEZ_val, grid,
                                                 fZs, kEZs, out);
}